// round 15
// baseline (speedup 1.0000x reference)
#include <cuda_runtime.h>
#include <cuda_bf16.h>
#include <cuda_fp16.h>
#include <stdint.h>

#define NB   8
#define MM   2048
#define DIN  64
#define DH   128
#define NODES (NB*MM)
#define KSPLIT 4

// scratch for gx as fp16, layout [n][i][h]
__device__ __align__(16) __half g_gh[NODES * DH];

// prepped weights:
//   f1: split-bf16 COMPACT (64 x 72)
//   f2: split-bf16 full    (64 x 136)
//   g : single fp16        (0=g1c, 1=g2[0:64], 2=g2[64:128]), 64 x 136
#define W_LDT  136
#define W1_LDT 72
__device__ __align__(16) __nv_bfloat16 pw_f1hi[64 * W1_LDT];
__device__ __align__(16) __nv_bfloat16 pw_f1lo[64 * W1_LDT];
__device__ __align__(16) __nv_bfloat16 pw_f2hi[64 * W_LDT];
__device__ __align__(16) __nv_bfloat16 pw_f2lo[64 * W_LDT];
__device__ __align__(16) __half        pw_g [3][64 * W_LDT];

// ---------------------------------------------------------------------------
#define LDSM_X4(r0,r1,r2,r3,addr) \
    asm volatile("ldmatrix.sync.aligned.m8n8.x4.shared.b16 {%0,%1,%2,%3}, [%4];" \
        : "=r"(r0),"=r"(r1),"=r"(r2),"=r"(r3) : "r"(addr))
#define LDSM_X4_T(r0,r1,r2,r3,addr) \
    asm volatile("ldmatrix.sync.aligned.m8n8.x4.trans.shared.b16 {%0,%1,%2,%3}, [%4];" \
        : "=r"(r0),"=r"(r1),"=r"(r2),"=r"(r3) : "r"(addr))
#define MMA16816(c,a,b) \
    asm volatile("mma.sync.aligned.m16n8k16.row.col.f32.bf16.bf16.f32 " \
        "{%0,%1,%2,%3}, {%4,%5,%6,%7}, {%8,%9}, {%0,%1,%2,%3};" \
        : "+f"(c[0]),"+f"(c[1]),"+f"(c[2]),"+f"(c[3]) \
        : "r"(a[0]),"r"(a[1]),"r"(a[2]),"r"(a[3]),"r"(b[0]),"r"(b[1]))
#define MMAF16(c,a,b) \
    asm volatile("mma.sync.aligned.m16n8k16.row.col.f32.f16.f16.f32 " \
        "{%0,%1,%2,%3}, {%4,%5,%6,%7}, {%8,%9}, {%0,%1,%2,%3};" \
        : "+f"(c[0]),"+f"(c[1]),"+f"(c[2]),"+f"(c[3]) \
        : "r"(a[0]),"r"(a[1]),"r"(a[2]),"r"(a[3]),"r"(b[0]),"r"(b[1]))
#define CP_ASYNC16(dst,src) \
    asm volatile("cp.async.cg.shared.global [%0], [%1], 16;" :: "r"(dst), "l"(src))
#define CP_COMMIT() asm volatile("cp.async.commit_group;")
#define CP_WAIT0()  asm volatile("cp.async.wait_group 0;")
#define CP_WAIT1()  asm volatile("cp.async.wait_group 1;")

__device__ __forceinline__ void split2(float v0, float v1, uint32_t& hi, uint32_t& lo)
{
    __nv_bfloat16 h0 = __float2bfloat16(v0);
    __nv_bfloat16 h1 = __float2bfloat16(v1);
    __nv_bfloat16 l0 = __float2bfloat16(v0 - __bfloat162float(h0));
    __nv_bfloat16 l1 = __float2bfloat16(v1 - __bfloat162float(h1));
    hi = (uint32_t)__bfloat16_as_ushort(h0) | ((uint32_t)__bfloat16_as_ushort(h1) << 16);
    lo = (uint32_t)__bfloat16_as_ushort(l0) | ((uint32_t)__bfloat16_as_ushort(l1) << 16);
}

__device__ __forceinline__ uint32_t pack_h2(float a, float b)
{
    __half2 h = __floats2half2_rn(a, b);
    return *(uint32_t*)&h;
}

// ===========================================================================
// Weight prep (unchanged from R14).
// ===========================================================================
__global__ void prep_kernel(
    const float* __restrict__ fw1, const float* __restrict__ fw2,
    const float* __restrict__ gw1, const float* __restrict__ gw2)
{
    const int tot = 2048 + 4096 + 3*4096;   // 18432 col-pairs
    for (int idx = blockIdx.x*blockDim.x + threadIdx.x; idx < tot;
         idx += gridDim.x*blockDim.x) {
        if (idx < 2048) {                   // f1 compact
            int k  = idx >> 5;
            int n2 = (idx & 31) * 2;
            uint32_t hi, lo;
            split2(fw1[k*64 + n2], fw1[k*64 + n2 + 1], hi, lo);
            *(uint32_t*)&pw_f1hi[k*W1_LDT + n2] = hi;
            *(uint32_t*)&pw_f1lo[k*W1_LDT + n2] = lo;
        } else if (idx < 6144) {            // f2
            int rem = idx - 2048;
            int k  = rem >> 6;
            int n2 = (rem & 63) * 2;
            uint32_t hi, lo;
            split2(fw2[k*128 + n2], fw2[k*128 + n2 + 1], hi, lo);
            *(uint32_t*)&pw_f2hi[k*W_LDT + n2] = hi;
            *(uint32_t*)&pw_f2lo[k*W_LDT + n2] = lo;
        } else {                            // g layers fp16
            int r   = idx - 6144;
            int gl  = r >> 12;
            int rem = r & 4095;
            int k   = rem >> 6;
            int n2  = (rem & 63) * 2;
            float v0, v1;
            if (gl == 0) {
                v0 = gw1[k*128 + n2]     + gw1[(k + 64)*128 + n2];
                v1 = gw1[k*128 + n2 + 1] + gw1[(k + 64)*128 + n2 + 1];
            } else if (gl == 1) {
                v0 = gw2[k*128 + n2];        v1 = gw2[k*128 + n2 + 1];
            } else {
                v0 = gw2[(k + 64)*128 + n2]; v1 = gw2[(k + 64)*128 + n2 + 1];
            }
            *(uint32_t*)&pw_g[gl][k*W_LDT + n2] = pack_h2(v0, v1);
        }
    }
}

// ===========================================================================
// Stage 1 shared pieces (unchanged from R14). 128-thread blocks, 32 rows.
// ===========================================================================
#define S1_T   128
#define S1_R   32
#define A0_LDT 72
#define A1_LDT 136
#define W_PS   (64*W_LDT)
#define W1_PS  (64*W1_LDT)
#define A0_PS  (S1_R*A0_LDT)
#define A1_PS  (S1_R*A1_LDT)

template<int NFR>
__device__ __forceinline__ void mma_pass(
    float acc[2][NFR][4],
    uint32_t aHiA, uint32_t aLoA, int aLDT, int kColOfs,
    uint32_t wHiA, uint32_t wLoA, int wLDT,
    int lane, int wn)
{
    const int arow = lane & 15;
    const int aq   = ((lane >> 4) & 1) * 8;
    #pragma unroll
    for (int ks = 0; ks < 4; ks++) {
        uint32_t ah[2][4], al[2][4];
        #pragma unroll
        for (int mf = 0; mf < 2; mf++) {
            uint32_t ao = (uint32_t)(((arow + mf*16)*aLDT + kColOfs + ks*16 + aq) * 2);
            LDSM_X4(ah[mf][0], ah[mf][1], ah[mf][2], ah[mf][3], aHiA + ao);
            LDSM_X4(al[mf][0], al[mf][1], al[mf][2], al[mf][3], aLoA + ao);
        }
        uint32_t bh[(NFR+1)/2][4], bl[(NFR+1)/2][4];
        #pragma unroll
        for (int nf2 = 0; nf2 < (NFR+1)/2; nf2++) {
            uint32_t bo = (uint32_t)((((ks*16) + (lane & 15))*wLDT + wn*NFR*8 + nf2*16 + aq) * 2);
            LDSM_X4_T(bh[nf2][0], bh[nf2][1], bh[nf2][2], bh[nf2][3], wHiA + bo);
            LDSM_X4_T(bl[nf2][0], bl[nf2][1], bl[nf2][2], bl[nf2][3], wLoA + bo);
        }
        #pragma unroll
        for (int mf = 0; mf < 2; mf++)
            #pragma unroll
            for (int nf = 0; nf < NFR; nf++) {
                uint32_t* bhf = &bh[nf>>1][(nf&1)*2];
                uint32_t* blf = &bl[nf>>1][(nf&1)*2];
                MMA16816(acc[mf][nf], ah[mf], bhf);
                MMA16816(acc[mf][nf], ah[mf], blf);
                MMA16816(acc[mf][nf], al[mf], bhf);
            }
    }
}

template<int NFR>
__device__ __forceinline__ void mma_pass_f16(
    float acc[2][NFR][4],
    uint32_t aA, int aLDT, int kColOfs,
    uint32_t wA,
    int lane, int wn)
{
    const int arow = lane & 15;
    const int aq   = ((lane >> 4) & 1) * 8;
    #pragma unroll
    for (int ks = 0; ks < 4; ks++) {
        uint32_t ah[2][4];
        #pragma unroll
        for (int mf = 0; mf < 2; mf++) {
            uint32_t ao = (uint32_t)(((arow + mf*16)*aLDT + kColOfs + ks*16 + aq) * 2);
            LDSM_X4(ah[mf][0], ah[mf][1], ah[mf][2], ah[mf][3], aA + ao);
        }
        uint32_t bh[(NFR+1)/2][4];
        #pragma unroll
        for (int nf2 = 0; nf2 < (NFR+1)/2; nf2++) {
            uint32_t bo = (uint32_t)((((ks*16) + (lane & 15))*W_LDT + wn*NFR*8 + nf2*16 + aq) * 2);
            LDSM_X4_T(bh[nf2][0], bh[nf2][1], bh[nf2][2], bh[nf2][3], wA + bo);
        }
        #pragma unroll
        for (int mf = 0; mf < 2; mf++)
            #pragma unroll
            for (int nf = 0; nf < NFR; nf++) {
                uint32_t* bhf = &bh[nf>>1][(nf&1)*2];
                MMAF16(acc[mf][nf], ah[mf], bhf);
            }
    }
}

template<int NFR>
__device__ __forceinline__ void init_bias(float acc[2][NFR][4],
    const float* __restrict__ b, int lane, int wn)
{
    #pragma unroll
    for (int nf = 0; nf < NFR; nf++) {
        int c = wn*NFR*8 + nf*8 + (lane & 3)*2;
        float b0 = b[c], b1 = b[c + 1];
        #pragma unroll
        for (int mf = 0; mf < 2; mf++) {
            acc[mf][nf][0] = b0; acc[mf][nf][1] = b1;
            acc[mf][nf][2] = b0; acc[mf][nf][3] = b1;
        }
    }
}

template<int NFR>
__device__ __forceinline__ void epi_relu_split(float acc[2][NFR][4],
    __nv_bfloat16* dHi, __nv_bfloat16* dLo, int ldt, int lane, int wn)
{
    #pragma unroll
    for (int mf = 0; mf < 2; mf++) {
        int r0 = mf*16 + (lane >> 2);
        #pragma unroll
        for (int nf = 0; nf < NFR; nf++) {
            int c = wn*NFR*8 + nf*8 + (lane & 3)*2;
            uint32_t hi, lo;
            split2(fmaxf(acc[mf][nf][0], 0.f), fmaxf(acc[mf][nf][1], 0.f), hi, lo);
            *(uint32_t*)&dHi[r0*ldt + c] = hi;
            *(uint32_t*)&dLo[r0*ldt + c] = lo;
            split2(fmaxf(acc[mf][nf][2], 0.f), fmaxf(acc[mf][nf][3], 0.f), hi, lo);
            *(uint32_t*)&dHi[(r0 + 8)*ldt + c] = hi;
            *(uint32_t*)&dLo[(r0 + 8)*ldt + c] = lo;
        }
    }
}

template<int NFR>
__device__ __forceinline__ void epi_relu_f16(float acc[2][NFR][4],
    __half* d, int ldt, int lane, int wn)
{
    #pragma unroll
    for (int mf = 0; mf < 2; mf++) {
        int r0 = mf*16 + (lane >> 2);
        #pragma unroll
        for (int nf = 0; nf < NFR; nf++) {
            int c = wn*NFR*8 + nf*8 + (lane & 3)*2;
            *(uint32_t*)&d[r0*ldt + c] =
                pack_h2(fmaxf(acc[mf][nf][0], 0.f), fmaxf(acc[mf][nf][1], 0.f));
            *(uint32_t*)&d[(r0 + 8)*ldt + c] =
                pack_h2(fmaxf(acc[mf][nf][2], 0.f), fmaxf(acc[mf][nf][3], 0.f));
        }
    }
}

__device__ __forceinline__ void weight_issue2(const void* srcH_, const void* srcL_,
    uint32_t wHiA, uint32_t wLoA, int bytes, int t)
{
    const uint8_t* srcH = (const uint8_t*)srcH_;
    const uint8_t* srcL = (const uint8_t*)srcL_;
    for (int idx = t; idx < bytes/16; idx += S1_T) {
        CP_ASYNC16(wHiA + idx*16, srcH + idx*16);
        CP_ASYNC16(wLoA + idx*16, srcL + idx*16);
    }
    CP_COMMIT();
}

__device__ __forceinline__ void weight_issue_g(int layer, uint32_t wA, int t)
{
    const uint8_t* src = (const uint8_t*)pw_g[layer];
    for (int idx = t; idx < (64*W_LDT*2)/16; idx += S1_T)
        CP_ASYNC16(wA + idx*16, src + idx*16);
    CP_COMMIT();
}

// ===========================================================================
// Stage 1 F (unchanged from R14)
// ===========================================================================
__global__ __launch_bounds__(S1_T) void stage1_f_kernel(
    const float* __restrict__ x,
    const float* __restrict__ fb1, const float* __restrict__ fb2,
    float* __restrict__ out)
{
    extern __shared__ __nv_bfloat16 s1[];
    __nv_bfloat16* wAHi = s1;
    __nv_bfloat16* wALo = wAHi + W1_PS;
    __nv_bfloat16* wBHi = wALo + W1_PS;
    __nv_bfloat16* wBLo = wBHi + W_PS;
    __nv_bfloat16* a0Hi = wBLo + W_PS;
    __nv_bfloat16* a0Lo = a0Hi + A0_PS;
    __nv_bfloat16* a1Hi = a0Lo + A0_PS;
    __nv_bfloat16* a1Lo = a1Hi + A0_PS;
    const uint32_t wAHiA = (uint32_t)__cvta_generic_to_shared(wAHi);
    const uint32_t wALoA = (uint32_t)__cvta_generic_to_shared(wALo);
    const uint32_t wBHiA = (uint32_t)__cvta_generic_to_shared(wBHi);
    const uint32_t wBLoA = (uint32_t)__cvta_generic_to_shared(wBLo);
    const uint32_t a0HiA = (uint32_t)__cvta_generic_to_shared(a0Hi);
    const uint32_t a0LoA = (uint32_t)__cvta_generic_to_shared(a0Lo);
    const uint32_t a1HiA = (uint32_t)__cvta_generic_to_shared(a1Hi);
    const uint32_t a1LoA = (uint32_t)__cvta_generic_to_shared(a1Lo);

    const int t = threadIdx.x, lane = t & 31, wid = t >> 5;
    const int wn = wid & 3;
    const int nodeBase = blockIdx.x * S1_R;

    weight_issue2(pw_f1hi, pw_f1lo, wAHiA, wALoA, 64*W1_LDT*2, t);
    weight_issue2(pw_f2hi, pw_f2lo, wBHiA, wBLoA, 64*W_LDT*2, t);

    for (int idx = t; idx < S1_R*64/2; idx += S1_T) {
        int r  = idx >> 5;
        int c2 = (idx & 31) * 2;
        float2 v = *(const float2*)&x[(size_t)(nodeBase + r)*DIN + c2];
        uint32_t hi, lo;
        split2(v.x, v.y, hi, lo);
        *(uint32_t*)&a0Hi[r*A0_LDT + c2] = hi;
        *(uint32_t*)&a0Lo[r*A0_LDT + c2] = lo;
    }

    CP_WAIT1();
    __syncthreads();
    {
        float acc[2][2][4];
        init_bias<2>(acc, fb1, lane, wn);
        mma_pass<2>(acc, a0HiA, a0LoA, A0_LDT, 0, wAHiA, wALoA, W1_LDT, lane, wn);
        epi_relu_split<2>(acc, a1Hi, a1Lo, A0_LDT, lane, wn);
    }
    CP_WAIT0();
    __syncthreads();
    {
        float acc[2][4][4];
        init_bias<4>(acc, fb2, lane, wn);
        mma_pass<4>(acc, a1HiA, a1LoA, A0_LDT, 0, wBHiA, wBLoA, W_LDT, lane, wn);
        #pragma unroll
        for (int mf = 0; mf < 2; mf++) {
            int r0 = nodeBase + mf*16 + (lane >> 2);
            #pragma unroll
            for (int nf = 0; nf < 4; nf++) {
                int c = wn*32 + nf*8 + (lane & 3)*2;
                *(float2*)&out[(size_t)r0*DH + c]       = make_float2(acc[mf][nf][0], acc[mf][nf][1]);
                *(float2*)&out[(size_t)(r0 + 8)*DH + c] = make_float2(acc[mf][nf][2], acc[mf][nf][3]);
            }
        }
    }
}

// ===========================================================================
// Stage 1 G (unchanged from R14)
// ===========================================================================
__global__ __launch_bounds__(S1_T) void stage1_g_kernel(
    const float* __restrict__ x,
    const float* __restrict__ gb1, const float* __restrict__ gb2)
{
    extern __shared__ __half sg[];
    __half* wGa = sg;
    __half* wGb = wGa + W_PS;
    __half* a0h = wGb + W_PS;
    __half* a1h = a0h + A0_PS;
    const uint32_t wGaA = (uint32_t)__cvta_generic_to_shared(wGa);
    const uint32_t wGbA = (uint32_t)__cvta_generic_to_shared(wGb);
    const uint32_t a0hA = (uint32_t)__cvta_generic_to_shared(a0h);
    const uint32_t a1hA = (uint32_t)__cvta_generic_to_shared(a1h);

    const int t = threadIdx.x, lane = t & 31, wid = t >> 5;
    const int wn = wid & 3;
    const int nodeBase = blockIdx.x * S1_R;

    weight_issue_g(0, wGaA, t);
    weight_issue_g(1, wGbA, t);

    for (int idx = t; idx < S1_R*64/2; idx += S1_T) {
        int r  = idx >> 5;
        int c2 = (idx & 31) * 2;
        float2 v = *(const float2*)&x[(size_t)(nodeBase + r)*DIN + c2];
        *(uint32_t*)&a0h[r*A0_LDT + c2] = pack_h2(v.x, v.y);
    }

    CP_WAIT1();
    __syncthreads();
    {
        float acc[2][4][4];
        init_bias<4>(acc, gb1, lane, wn);
        mma_pass_f16<4>(acc, a0hA, A0_LDT, 0, wGaA, lane, wn);
        epi_relu_f16<4>(acc, a1h, A1_LDT, lane, wn);
    }
    __syncthreads();
    weight_issue_g(2, wGaA, t);

    float acc[2][4][4];
    init_bias<4>(acc, gb2, lane, wn);
    CP_WAIT1();
    __syncthreads();
    mma_pass_f16<4>(acc, a1hA, A1_LDT, 0, wGbA, lane, wn);
    CP_WAIT0();
    __syncthreads();
    mma_pass_f16<4>(acc, a1hA, A1_LDT, 64, wGaA, lane, wn);

    #pragma unroll
    for (int mf = 0; mf < 2; mf++) {
        int r0 = nodeBase + mf*16 + (lane >> 2);
        #pragma unroll
        for (int nf = 0; nf < 4; nf++) {
            int c = wn*32 + nf*8 + (lane & 3)*2;
            *(uint32_t*)&g_gh[(size_t)r0*DH + c] =
                pack_h2(acc[mf][nf][0], acc[mf][nf][1]);
            *(uint32_t*)&g_gh[(size_t)(r0 + 8)*DH + c] =
                pack_h2(acc[mf][nf][2], acc[mf][nf][3]);
        }
    }
}

// ===========================================================================
// Stage 2: pure fp16 1-term, 3-stage pipeline, register-dieted for 4 CTA/SM.
// E prefetch distance-1 (single erA reg set); E loader 8 floats/thread
// (2x LDG.128, 1x STS.128). launch_bounds(256,4) caps regs at 64.
// ===========================================================================
#define BK    32
#define EPAD  72
#define GPAD  136
#define SE_PS (BK*EPAD)
#define SG_PS (BK*GPAD)
#define KITER (MM/(BK*KSPLIT))     // 16

__global__ __launch_bounds__(256, 4) void stage2_kernel(
    const float* __restrict__ edge, float* __restrict__ out)
{
    extern __shared__ __half sm2[];
    __half* sE = sm2;                   // [3 buf][BK][EPAD]
    __half* sG = sm2 + 3*SE_PS;         // [3 buf][BK][GPAD]

    const int n  = blockIdx.y;
    const int j0 = blockIdx.x * 64;
    const int koff = blockIdx.z * (MM / KSPLIT);
    const int t = threadIdx.x, lane = t & 31, wid = t >> 5;
    const int wm = wid >> 2, wn = wid & 3;

    const float* eg = edge + (size_t)n*MM*MM + j0;
    const __half* gh = g_gh + (size_t)n*MM*DH;

    const uint32_t sEb = (uint32_t)__cvta_generic_to_shared(sE);
    const uint32_t sGb = (uint32_t)__cvta_generic_to_shared(sG);

    const int erow = t >> 3;           // 0..31 (E loader row)
    const int ecol = (t & 7) * 8;      // E loader col (8 floats)
    const int grow = t >> 4;           // 0..15 (+16) (G loader row)
    const int gcol = (t & 15) * 8;     // G loader 16B col

    const int arow_off = ((lane >> 4) & 1)*8 + (lane & 7);
    const int aq1      = ((lane >> 3) & 1)*8;
    const int bq       = ((lane >> 4) & 1)*8;

    float acc[2][4][4];
    #pragma unroll
    for (int a = 0; a < 2; a++)
        #pragma unroll
        for (int b = 0; b < 4; b++)
            #pragma unroll
            for (int c = 0; c < 4; c++) acc[a][b][c] = 0.f;

    float4 erA[2];   // one E chunk: 8 floats (row erow, cols ecol..ecol+7)

    // ---- prologue ----
    // G chunks 0,1 (groups 0,1)
    #pragma unroll
    for (int c = 0; c < 2; c++) {
        #pragma unroll
        for (int u = 0; u < 2; u++) {
            int row = grow + u*16;
            CP_ASYNC16(sGb + (uint32_t)((c*BK + row)*GPAD + gcol)*2,
                       gh + (size_t)(koff + c*BK + row)*DH + gcol);
        }
        CP_COMMIT();
    }
    // E chunk 0: LDG -> STS directly
    {
        const float* ep = &eg[(size_t)(koff + erow)*MM + ecol];
        float4 v0 = *(const float4*)ep;
        float4 v1 = *(const float4*)(ep + 4);
        uint4 pk;
        pk.x = pack_h2(v0.x, v0.y); pk.y = pack_h2(v0.z, v0.w);
        pk.z = pack_h2(v1.x, v1.y); pk.w = pack_h2(v1.z, v1.w);
        *(uint4*)&sE[(0*BK + erow)*EPAD + ecol] = pk;
    }
    // E chunk 1 -> regs
    {
        const float* ep = &eg[(size_t)(koff + BK + erow)*MM + ecol];
        erA[0] = *(const float4*)ep;
        erA[1] = *(const float4*)(ep + 4);
    }

    CP_WAIT1();
    __syncthreads();

    for (int kt = 0; kt < KITER; kt++) {
        const int b = kt % 3;

        // 1. G prefetch chunk kt+2
        if (kt + 2 < KITER) {
            const int i0 = koff + (kt + 2) * BK;
            const int gb = (kt + 2) % 3;
            #pragma unroll
            for (int u = 0; u < 2; u++) {
                int row = grow + u*16;
                CP_ASYNC16(sGb + (uint32_t)((gb*BK + row)*GPAD + gcol)*2,
                           gh + (size_t)(i0 + row)*DH + gcol);
            }
            CP_COMMIT();
        }

        // 2. store E chunk kt+1 (erA) into ebuf (kt+1)%3
        if (kt + 1 < KITER) {
            const int eb = (kt + 1) % 3;
            uint4 pk;
            pk.x = pack_h2(erA[0].x, erA[0].y); pk.y = pack_h2(erA[0].z, erA[0].w);
            pk.z = pack_h2(erA[1].x, erA[1].y); pk.w = pack_h2(erA[1].z, erA[1].w);
            *(uint4*)&sE[(eb*BK + erow)*EPAD + ecol] = pk;
        }

        // 3. LDG E chunk kt+2 into erA (distance-1)
        if (kt + 2 < KITER) {
            const float* ep = &eg[(size_t)(koff + (kt + 2)*BK + erow)*MM + ecol];
            erA[0] = *(const float4*)ep;
            erA[1] = *(const float4*)(ep + 4);
        }

        // 4. compute on buffer b
        #pragma unroll
        for (int ks = 0; ks < BK; ks += 16) {
            uint32_t ah[2][4];
            #pragma unroll
            for (int mf = 0; mf < 2; mf++) {
                int acol = wm*32 + mf*16 + aq1;
                uint32_t a0 = sEb + (uint32_t)(((b*BK + ks + arow_off)*EPAD + acol)*2);
                LDSM_X4_T(ah[mf][0], ah[mf][1], ah[mf][2], ah[mf][3], a0);
            }
            uint32_t bh[2][4];
            #pragma unroll
            for (int nf2 = 0; nf2 < 2; nf2++) {
                int bcol = wn*32 + nf2*16 + bq;
                uint32_t b0 = sGb + (uint32_t)(((b*BK + ks + (lane & 15))*GPAD + bcol)*2);
                LDSM_X4_T(bh[nf2][0], bh[nf2][1], bh[nf2][2], bh[nf2][3], b0);
            }
            #pragma unroll
            for (int mf = 0; mf < 2; mf++)
                #pragma unroll
                for (int nf = 0; nf < 4; nf++) {
                    uint32_t* bhf = &bh[nf>>1][(nf&1)*2];
                    MMAF16(acc[mf][nf], ah[mf], bhf);
                }
        }

        // 5. G chunk kt+1 arrived (kt+2 group may pend)
        CP_WAIT1();
        __syncthreads();
    }

    // epilogue: atomic add into out (commutative across K-quarters)
    #pragma unroll
    for (int mf = 0; mf < 2; mf++) {
        int r0 = j0 + wm*32 + mf*16 + (lane >> 2);
        #pragma unroll
        for (int nf = 0; nf < 4; nf++) {
            int c = wn*32 + nf*8 + (lane & 3)*2;
            size_t o0 = ((size_t)n*MM + r0)*DH + c;
            size_t o1 = o0 + (size_t)8*DH;
            atomicAdd(&out[o0],     acc[mf][nf][0]);
            atomicAdd(&out[o0 + 1], acc[mf][nf][1]);
            atomicAdd(&out[o1],     acc[mf][nf][2]);
            atomicAdd(&out[o1 + 1], acc[mf][nf][3]);
        }
    }
}

// ---------------------------------------------------------------------------
extern "C" void kernel_launch(void* const* d_in, const int* in_sizes, int n_in,
                              void* d_out, int out_size)
{
    const float* x    = (const float*)d_in[0];
    const float* edge = (const float*)d_in[1];
    const float* fw1  = (const float*)d_in[2];
    const float* fb1  = (const float*)d_in[3];
    const float* fw2  = (const float*)d_in[4];
    const float* fb2  = (const float*)d_in[5];
    const float* gw1  = (const float*)d_in[6];
    const float* gb1  = (const float*)d_in[7];
    const float* gw2  = (const float*)d_in[8];
    const float* gb2  = (const float*)d_in[9];
    float* out = (float*)d_out;

    const int SMEM_F = (2*W1_PS + 2*W_PS + 4*A0_PS) * 2;   // 71680 B
    const int SMEM_G = (2*W_PS + A0_PS + A1_PS) * 2;       // 48128 B
    const int SMEM2  = (3*SE_PS + 3*SG_PS) * 2;            // 39936 B

    cudaFuncSetAttribute(stage1_f_kernel, cudaFuncAttributeMaxDynamicSharedMemorySize, SMEM_F);
    cudaFuncSetAttribute(stage1_g_kernel, cudaFuncAttributeMaxDynamicSharedMemorySize, SMEM_G);
    cudaFuncSetAttribute(stage2_kernel,   cudaFuncAttributeMaxDynamicSharedMemorySize, SMEM2);

    prep_kernel<<<144, 256>>>(fw1, fw2, gw1, gw2);
    stage1_g_kernel<<<512, S1_T, SMEM_G>>>(x, gb1, gb2);
    stage1_f_kernel<<<512, S1_T, SMEM_F>>>(x, fb1, fb2, out);
    stage2_kernel<<<dim3(32, NB, KSPLIT), 256, SMEM2>>>(edge, out);
}